// round 1
// baseline (speedup 1.0000x reference)
#include <cuda_runtime.h>
#include <math.h>

#define NB 8
#define NT 2048
#define NE 64
#define NH 8
#define NDK 8
#define NFF 256
#define NROWS (NB*NT)

typedef unsigned long long u64;

__device__ __forceinline__ u64 pk2(float x, float y){ u64 r; asm("mov.b64 %0,{%1,%2};":"=l"(r):"f"(x),"f"(y)); return r; }
__device__ __forceinline__ void upk2(float&x,float&y,u64 v){ asm("mov.b64 {%0,%1},%2;":"=f"(x),"=f"(y):"l"(v)); }
__device__ __forceinline__ u64 ffma2(u64 a,u64 b,u64 c){ u64 r; asm("fma.rn.f32x2 %0,%1,%2,%3;":"=l"(r):"l"(a),"l"(b),"l"(c)); return r; }
__device__ __forceinline__ u64 fadd2(u64 a,u64 b){ u64 r; asm("add.rn.f32x2 %0,%1,%2;":"=l"(r):"l"(a),"l"(b)); return r; }

// ---- scratch (device globals: no allocation allowed) ----
__device__ float g_q[NB*NH*NT*NDK];     // [b][h][t][d], pre-scaled by 1/sqrt(DK)
__device__ float g_k[NB*NH*NDK*NT];     // [b][h][d][t]  (t contiguous for packed s-pairs)
__device__ float g_v[NB*NH*NDK*NT];     // [b][h][d][t]
__device__ float g_attn[NROWS*NE];
__device__ float g_x1[NROWS*NE];
__device__ float g_qout[NROWS*NE];
__device__ float g_hid[NROWS*NFF];
__device__ float g_W1t[NE*NFF];         // W1 transposed: [e][f]
__device__ float g_W2t[NFF*NE];         // W2 transposed: [f][j]

// ---- tiny weight transpose (avoids all smem bank-conflict transposes in FFN) ----
__global__ void k_transpose(const float* __restrict__ W1, const float* __restrict__ W2){
    int i = blockIdx.x*256 + threadIdx.x;
    if (i < NE*NFF){
        int e = i / NFF, f = i % NFF;        // W1t[e][f] = W1[f][e]
        g_W1t[i] = W1[f*NE + e];
        int f2 = i / NE, j = i % NE;         // W2t[f][j] = W2[j][f]
        g_W2t[i] = W2[j*NFF + f2];
    }
}

// ---- K1: QKV projection + cos(. + theta) ----
__global__ __launch_bounds__(256) void k_qkv(
    const float* __restrict__ x,
    const float* __restrict__ Wq, const float* __restrict__ bq,
    const float* __restrict__ Wk, const float* __restrict__ bk,
    const float* __restrict__ Wv, const float* __restrict__ bv,
    const float* __restrict__ th)
{
    __shared__ float Wt[64][65];   // transposed weight, pad 65 -> conflict free
    __shared__ float xs[16][64];
    __shared__ float bs[64];
    int tid = threadIdx.x;
    int row0 = blockIdx.x*16;
    for (int i = tid; i < 16*64; i += 256) (&xs[0][0])[i] = x[row0*NE + i];
    const float theta = *th;
    int g = tid >> 6;     // 0..3 (row group)
    int j = tid & 63;     // output column
    const float* Ws[3] = {Wq, Wk, Wv};
    const float* bias[3] = {bq, bk, bv};
    for (int p = 0; p < 3; ++p){
        __syncthreads();
        for (int i = tid; i < 4096; i += 256){
            Wt[i & 63][i >> 6] = Ws[p][i];   // Wt[e][j] = W[j][e]
        }
        if (tid < 64) bs[tid] = bias[p][tid];
        __syncthreads();
        float acc0=0.f, acc1=0.f, acc2=0.f, acc3=0.f;
        #pragma unroll
        for (int e = 0; e < 64; ++e){
            float w = Wt[e][j];
            acc0 = fmaf(xs[g     ][e], w, acc0);
            acc1 = fmaf(xs[g + 4 ][e], w, acc1);
            acc2 = fmaf(xs[g + 8 ][e], w, acc2);
            acc3 = fmaf(xs[g + 12][e], w, acc3);
        }
        float accs[4] = {acc0, acc1, acc2, acc3};
        int h = j >> 3, d = j & 7;
        #pragma unroll
        for (int r = 0; r < 4; ++r){
            int row = row0 + g + r*4;
            int b = row >> 11, t = row & (NT-1);
            float val = cosf(accs[r] + bs[j] + theta);
            if (p == 0)
                g_q[((b*NH + h)*NT + t)*NDK + d] = val * 0.35355339059327373f; // 1/sqrt(8)
            else {
                float* dst = (p == 1) ? g_k : g_v;
                dst[((b*NH + h)*NDK + d)*NT + t] = val;
            }
        }
    }
}

// ---- K2: flash-style attention, full K/V in smem, no-max single-pass softmax ----
// scores bounded: |q.k|/sqrt(8) <= 2.83 -> exp safe in fp32 without max subtraction.
__global__ void __launch_bounds__(512,1) k_attn()
{
    extern __shared__ float sm[];
    float* Ks = sm;                 // [8][2048]
    float* Vs = sm + NDK*NT;        // [8][2048]
    int bh  = blockIdx.y;
    int tid = threadIdx.x;
    const float* kg = g_k + bh*(NDK*NT);
    const float* vg = g_v + bh*(NDK*NT);
    for (int i = tid; i < NDK*NT/4; i += 512){
        ((float4*)Ks)[i] = ((const float4*)kg)[i];
        ((float4*)Vs)[i] = ((const float4*)vg)[i];
    }
    __syncthreads();

    int q0 = blockIdx.x*1024 + tid;       // queries q0 and q0+512
    u64 q2[2][8], o2[2][8], lsum[2];
    #pragma unroll
    for (int qq = 0; qq < 2; ++qq){
        const float* qp = g_q + (bh*NT + (q0 + qq*512))*NDK;
        #pragma unroll
        for (int d = 0; d < 8; ++d){ float qv = qp[d]; q2[qq][d] = pk2(qv, qv); }
        #pragma unroll
        for (int d = 0; d < 8; ++d) o2[qq][d] = 0ull;
        lsum[qq] = 0ull;
    }

    #pragma unroll 1
    for (int s = 0; s < NT; s += 4){
        u64 sA[2], sB[2];
        sA[0]=0ull; sA[1]=0ull; sB[0]=0ull; sB[1]=0ull;
        #pragma unroll
        for (int d = 0; d < 8; ++d){
            float4 k4 = *(const float4*)(Ks + d*NT + s);
            u64 kab = pk2(k4.x, k4.y);
            u64 kcd = pk2(k4.z, k4.w);
            #pragma unroll
            for (int qq = 0; qq < 2; ++qq){
                sA[qq] = ffma2(q2[qq][d], kab, sA[qq]);
                sB[qq] = ffma2(q2[qq][d], kcd, sB[qq]);
            }
        }
        u64 pA[2], pB[2];
        #pragma unroll
        for (int qq = 0; qq < 2; ++qq){
            float a,b,c,d2;
            upk2(a, b, sA[qq]); upk2(c, d2, sB[qq]);
            a = __expf(a); b = __expf(b); c = __expf(c); d2 = __expf(d2);
            pA[qq] = pk2(a, b); pB[qq] = pk2(c, d2);
            lsum[qq] = fadd2(lsum[qq], fadd2(pA[qq], pB[qq]));
        }
        #pragma unroll
        for (int d = 0; d < 8; ++d){
            float4 v4 = *(const float4*)(Vs + d*NT + s);
            u64 vab = pk2(v4.x, v4.y);
            u64 vcd = pk2(v4.z, v4.w);
            #pragma unroll
            for (int qq = 0; qq < 2; ++qq){
                o2[qq][d] = ffma2(pA[qq], vab, o2[qq][d]);
                o2[qq][d] = ffma2(pB[qq], vcd, o2[qq][d]);
            }
        }
    }

    int b = bh >> 3, h = bh & 7;
    #pragma unroll
    for (int qq = 0; qq < 2; ++qq){
        float lx, ly; upk2(lx, ly, lsum[qq]);
        float inv = 1.0f / (lx + ly);
        int t = q0 + qq*512;
        float* dst = g_attn + (b*NT + t)*NE + h*8;
        #pragma unroll
        for (int d = 0; d < 8; ++d){
            float ox, oy; upk2(ox, oy, o2[qq][d]);
            dst[d] = (ox + oy) * inv;
        }
    }
}

// ---- K3: Wo projection + residual + LN1 + qout = cos(x1)*cos(theta_ffn) ----
__global__ __launch_bounds__(256) void k_o_ln(
    const float* __restrict__ x, const float* __restrict__ Wo,
    const float* __restrict__ bo, const float* __restrict__ g1,
    const float* __restrict__ be1, const float* __restrict__ th)
{
    __shared__ float Wt[64][65];
    __shared__ float as[8][64];
    __shared__ float xs[8][64];
    int tid = threadIdx.x;
    int row0 = blockIdx.x*8;
    for (int i = tid; i < 4096; i += 256) Wt[i & 63][i >> 6] = Wo[i];
    for (int i = tid; i < 512; i += 256){
        (&as[0][0])[i] = g_attn[row0*NE + i];
        (&xs[0][0])[i] = x[row0*NE + i];
    }
    __syncthreads();
    int r = tid >> 5, lane = tid & 31;
    float a0 = 0.f, a1 = 0.f;
    #pragma unroll
    for (int e = 0; e < 64; ++e){
        float av = as[r][e];
        a0 = fmaf(av, Wt[e][lane],      a0);
        a1 = fmaf(av, Wt[e][lane + 32], a1);
    }
    a0 += bo[lane]      + xs[r][lane];
    a1 += bo[lane + 32] + xs[r][lane + 32];
    float s = a0 + a1;
    #pragma unroll
    for (int o = 16; o > 0; o >>= 1) s += __shfl_xor_sync(0xffffffffu, s, o);
    float mean = s * (1.0f/64.0f);
    float d0 = a0 - mean, d1 = a1 - mean;
    float vs = d0*d0 + d1*d1;
    #pragma unroll
    for (int o = 16; o > 0; o >>= 1) vs += __shfl_xor_sync(0xffffffffu, vs, o);
    float rstd = rsqrtf(vs * (1.0f/64.0f) + 1e-5f);
    float y0 = d0*rstd*g1[lane]      + be1[lane];
    float y1 = d1*rstd*g1[lane + 32] + be1[lane + 32];
    int row = row0 + r;
    g_x1[row*NE + lane]      = y0;
    g_x1[row*NE + lane + 32] = y1;
    float ct = cosf(*th);
    g_qout[row*NE + lane]      = cosf(y0)*ct;
    g_qout[row*NE + lane + 32] = cosf(y1)*ct;
}

// ---- K4: FFN layer 1: hid = relu(qout @ W1^T + b1) ----
__global__ __launch_bounds__(256) void k_ffn1(const float* __restrict__ b1)
{
    extern __shared__ float sm[];
    float* Ws = sm;                  // W1t [64][256]
    float* xs = sm + NE*NFF;         // [32][64]
    int tid = threadIdx.x;
    int row0 = blockIdx.x*32;
    for (int i = tid; i < NE*NFF/4; i += 256) ((float4*)Ws)[i] = ((const float4*)g_W1t)[i];
    for (int i = tid; i < 32*NE/4;  i += 256) ((float4*)xs)[i] = ((const float4*)(g_qout + row0*NE))[i];
    __syncthreads();
    int rg = tid >> 6;      // 0..3 -> rows rg*8 .. rg*8+7
    int cg = tid & 63;      // cols cg*4 .. cg*4+3
    float acc[8][4];
    #pragma unroll
    for (int i = 0; i < 8; ++i){ acc[i][0]=0.f; acc[i][1]=0.f; acc[i][2]=0.f; acc[i][3]=0.f; }
    #pragma unroll 4
    for (int e = 0; e < 64; ++e){
        float4 w4 = *(const float4*)(Ws + e*NFF + cg*4);
        #pragma unroll
        for (int i = 0; i < 8; ++i){
            float xv = xs[(rg*8 + i)*NE + e];
            acc[i][0] = fmaf(xv, w4.x, acc[i][0]);
            acc[i][1] = fmaf(xv, w4.y, acc[i][1]);
            acc[i][2] = fmaf(xv, w4.z, acc[i][2]);
            acc[i][3] = fmaf(xv, w4.w, acc[i][3]);
        }
    }
    float b0 = b1[cg*4], bb1 = b1[cg*4+1], b2v = b1[cg*4+2], b3 = b1[cg*4+3];
    #pragma unroll
    for (int i = 0; i < 8; ++i){
        int row = row0 + rg*8 + i;
        float4 o;
        o.x = fmaxf(acc[i][0] + b0,  0.f);
        o.y = fmaxf(acc[i][1] + bb1, 0.f);
        o.z = fmaxf(acc[i][2] + b2v, 0.f);
        o.w = fmaxf(acc[i][3] + b3,  0.f);
        *(float4*)(g_hid + row*NFF + cg*4) = o;
    }
}

// ---- K5: FFN layer 2 + residual + LN2 -> out ----
__global__ __launch_bounds__(256) void k_ffn2(
    const float* __restrict__ b2, const float* __restrict__ g2,
    const float* __restrict__ be2, float* __restrict__ out)
{
    extern __shared__ float sm[];
    float* Ws = sm;                  // W2t [256][64]
    float* hs = sm + NFF*NE;         // [32][256]
    int tid = threadIdx.x;
    int row0 = blockIdx.x*32;
    for (int i = tid; i < NFF*NE/4; i += 256) ((float4*)Ws)[i] = ((const float4*)g_W2t)[i];
    for (int i = tid; i < 32*NFF/4; i += 256) ((float4*)hs)[i] = ((const float4*)(g_hid + row0*NFF))[i];
    __syncthreads();
    int wr = tid >> 5, lane = tid & 31;
    #pragma unroll 1
    for (int rr = 0; rr < 4; ++rr){
        int r = rr*8 + wr;
        const float* hrow = hs + r*NFF;
        float a0 = 0.f, a1 = 0.f;
        #pragma unroll 8
        for (int f = 0; f < NFF; ++f){
            float hv = hrow[f];
            a0 = fmaf(hv, Ws[f*64 + lane],      a0);
            a1 = fmaf(hv, Ws[f*64 + lane + 32], a1);
        }
        int row = row0 + r;
        float r0 = g_x1[row*NE + lane], r1 = g_x1[row*NE + lane + 32];
        a0 += b2[lane]      + r0;
        a1 += b2[lane + 32] + r1;
        float s = a0 + a1;
        #pragma unroll
        for (int o = 16; o > 0; o >>= 1) s += __shfl_xor_sync(0xffffffffu, s, o);
        float mean = s * (1.0f/64.0f);
        float d0 = a0 - mean, d1 = a1 - mean;
        float vs = d0*d0 + d1*d1;
        #pragma unroll
        for (int o = 16; o > 0; o >>= 1) vs += __shfl_xor_sync(0xffffffffu, vs, o);
        float rstd = rsqrtf(vs * (1.0f/64.0f) + 1e-5f);
        out[row*NE + lane]      = d0*rstd*g2[lane]      + be2[lane];
        out[row*NE + lane + 32] = d1*rstd*g2[lane + 32] + be2[lane + 32];
    }
}

extern "C" void kernel_launch(void* const* d_in, const int* in_sizes, int n_in,
                              void* d_out, int out_size)
{
    const float* x   = (const float*)d_in[0];
    const float* Wq  = (const float*)d_in[1];
    const float* bq  = (const float*)d_in[2];
    const float* Wk  = (const float*)d_in[3];
    const float* bk  = (const float*)d_in[4];
    const float* Wv  = (const float*)d_in[5];
    const float* bv  = (const float*)d_in[6];
    const float* Wo  = (const float*)d_in[7];
    const float* bo  = (const float*)d_in[8];
    const float* tha = (const float*)d_in[9];
    const float* thf = (const float*)d_in[10];
    const float* W1  = (const float*)d_in[11];
    const float* b1  = (const float*)d_in[12];
    const float* W2  = (const float*)d_in[13];
    const float* b2  = (const float*)d_in[14];
    const float* g1  = (const float*)d_in[15];
    const float* be1 = (const float*)d_in[16];
    const float* g2  = (const float*)d_in[17];
    const float* be2 = (const float*)d_in[18];
    float* out = (float*)d_out;

    cudaFuncSetAttribute(k_attn, cudaFuncAttributeMaxDynamicSharedMemorySize, 131072);
    cudaFuncSetAttribute(k_ffn1, cudaFuncAttributeMaxDynamicSharedMemorySize, 73728);
    cudaFuncSetAttribute(k_ffn2, cudaFuncAttributeMaxDynamicSharedMemorySize, 98304);

    k_transpose<<<64, 256>>>(W1, W2);
    k_qkv<<<NROWS/16, 256>>>(x, Wq, bq, Wk, bk, Wv, bv, tha);
    k_attn<<<dim3(2, 64), 512, 131072>>>();
    k_o_ln<<<NROWS/8, 256>>>(x, Wo, bo, g1, be1, thf);
    k_ffn1<<<NROWS/32, 256, 73728>>>(b1);
    k_ffn2<<<NROWS/32, 256, 98304>>>(b2, g2, be2, out);
}